// round 15
// baseline (speedup 1.0000x reference)
#include <cuda_runtime.h>
#include <cuda_bf16.h>
#include <cstdint>

#define BATCH 4096
#define D 128
#define TM 128
#define TN 128
#define NTHR 256
#define NTILE 528       // 496 strict-upper + 32 diag
#define NPERS 296       // 2 CTAs x 148 SMs
#define NPART 512

// ---- device scratch (no allocations allowed) ----
__device__ unsigned char g_f8[BATCH * D];    // e4m3, pre-scaled by sqrt(1/T)
__device__ unsigned long long g_bits[BATCH];
__device__ float g_rcnt[BATCH];              // 1/cnt (0 if cnt==0)
__device__ float g_diag[BATCH];              // ||f||^2 / T == row shift (exact f32)
__device__ float4 g_row4[BATCH * 64];        // {S,A,W,P} row partials, chunk=jt*2+wc
__device__ float4 g_col4[BATCH * 128];       // col partials, chunk=it*4+wr
__device__ float g_part[NPART];
__device__ int g_sem;
__device__ int g_tick;

__device__ __forceinline__ uint32_t smem_u32(const void* p) {
    uint32_t a;
    asm("{ .reg .u64 t; cvta.to.shared.u64 t, %1; cvt.u32.u64 %0, t; }" : "=r"(a) : "l"(p));
    return a;
}
__device__ __forceinline__ void ldm_x4(uint32_t& r0, uint32_t& r1, uint32_t& r2, uint32_t& r3,
                                       uint32_t a) {
    asm volatile("ldmatrix.sync.aligned.m8n8.x4.shared.b16 {%0,%1,%2,%3}, [%4];"
                 : "=r"(r0), "=r"(r1), "=r"(r2), "=r"(r3) : "r"(a));
}
__device__ __forceinline__ void mma16832(float* c, const uint32_t* a, uint32_t b0, uint32_t b1) {
    asm volatile(
        "mma.sync.aligned.m16n8k32.row.col.f32.e4m3.e4m3.f32 "
        "{%0,%1,%2,%3}, {%4,%5,%6,%7}, {%8,%9}, {%0,%1,%2,%3};"
        : "+f"(c[0]), "+f"(c[1]), "+f"(c[2]), "+f"(c[3])
        : "r"(a[0]), "r"(a[1]), "r"(a[2]), "r"(a[3]), "r"(b0), "r"(b1));
}
__device__ __forceinline__ uint32_t swz8(int row, int c16) {
    return (uint32_t)(row * 128 + ((c16 ^ (row & 7)) << 4));
}

#define SQRT_INVT 3.7796447300922722f
#define INVT 14.285714285714286f

// ======================= k1: fused prep (1 row/warp, 512 CTAs — measured best) ==========
__global__ void prep_rows(const float* __restrict__ F, const float* __restrict__ L) {
    const int lane = threadIdx.x & 31, w = threadIdx.x >> 5;
    const int row = blockIdx.x * 8 + w;
    if (blockIdx.x == 0 && threadIdx.x == 0) { g_sem = 0; g_tick = 0; }

    float4 v = *(const float4*)(F + (size_t)row * D + lane * 4);
    float d = v.x * v.x + v.y * v.y + v.z * v.z + v.w * v.w;
#pragma unroll
    for (int o = 16; o > 0; o >>= 1) d += __shfl_xor_sync(0xffffffffu, d, o);

    uint16_t lo, hi;
    asm("cvt.rn.satfinite.e4m3x2.f32 %0, %1, %2;"
        : "=h"(lo) : "f"(v.y * SQRT_INVT), "f"(v.x * SQRT_INVT));
    asm("cvt.rn.satfinite.e4m3x2.f32 %0, %1, %2;"
        : "=h"(hi) : "f"(v.w * SQRT_INVT), "f"(v.z * SQRT_INVT));
    *(uint32_t*)(g_f8 + (size_t)row * D + lane * 4) = (uint32_t)lo | ((uint32_t)hi << 16);

    float l0 = L[row * 50 + lane];
    float l1 = (lane < 18) ? L[row * 50 + 32 + lane] : 0.f;
    unsigned b0 = __ballot_sync(0xffffffffu, l0 > 0.5f);
    unsigned b1 = __ballot_sync(0xffffffffu, l1 > 0.5f) & 0x3ffffu;

    if (lane == 0) {
        g_bits[row] = (unsigned long long)b0 | ((unsigned long long)b1 << 32);
        float cnt = (float)(__popc(b0) + __popc(b1));
        g_rcnt[row] = (cnt > 0.f) ? __fdividef(1.f, cnt) : 0.f;
        g_diag[row] = d * INVT;
    }
}

// ======================= epilogue (R12/R14 exact — shuffle reductions only) =============
// FAST: whole-tile underflow screen passed -> S identically 0, no shifts/exp/cS.
__device__ __forceinline__ void epilogue_fast(
    const float (&acc)[2][8][4], const int (&gi4)[4], const unsigned long long (&bi4)[4],
    const float (&rci4)[4], int it, int jt, int wr, int wc, int lane,
    const unsigned long long* bitsJ, const float* rcJ) {
    const int sub = lane & 3;
    const int colbase = wc * 64;

    float rA[4] = {0, 0, 0, 0}, rW[4] = {0, 0, 0, 0}, rP[4] = {0, 0, 0, 0};
#pragma unroll
    for (int n = 0; n < 8; n++) {
#pragma unroll
        for (int e = 0; e < 2; e++) {
            const int jl = colbase + n * 8 + sub * 2 + e;
            const unsigned long long bj = bitsJ[jl];
            const float rcj = rcJ[jl];
            float cA = 0.f, cW = 0.f, cP = 0.f;
#pragma unroll
            for (int g = 0; g < 4; g++) {
                const float x = acc[g >> 1][n][(g & 1) * 2 + e];
                const float inter = (float)__popcll(bi4[g] & bj);
                const float mu = inter * fminf(rci4[g], rcj);
                const float tv = mu * x;
                const float one = fminf(inter, 1.f);
                rA[g] += tv; rW[g] += mu; rP[g] += one;
                cA += tv; cW += mu; cP += one;
            }
#pragma unroll
            for (int o = 4; o <= 16; o <<= 1) {
                cA += __shfl_xor_sync(0xffffffffu, cA, o);
                cW += __shfl_xor_sync(0xffffffffu, cW, o);
                cP += __shfl_xor_sync(0xffffffffu, cP, o);
            }
            if ((lane >> 2) == 0)
                g_col4[(jt * TN + jl) * 128 + it * 4 + wr] = make_float4(0.f, cA, cW, cP);
        }
    }
#pragma unroll
    for (int g = 0; g < 4; g++) {
        float A = rA[g], W = rW[g], P = rP[g];
#pragma unroll
        for (int o = 1; o < 4; o <<= 1) {
            A += __shfl_xor_sync(0xffffffffu, A, o);
            W += __shfl_xor_sync(0xffffffffu, W, o);
            P += __shfl_xor_sync(0xffffffffu, P, o);
        }
        if (sub == 0)
            g_row4[gi4[g] * 64 + jt * 2 + wc] = make_float4(0.f, A, W, P);
    }
}

// SLOW: exact per-element guards (diag tiles and any tile failing the screen).
template <bool DG>
__device__ __forceinline__ void epilogue_slow(
    const float (&acc)[2][8][4], const int (&gi4)[4], const unsigned long long (&bi4)[4],
    const float (&rci4)[4], const float (&di4)[4], int i0, int j0, int it, int jt,
    int wr, int wc, int lane,
    const unsigned long long* bitsJ, const float* rcJ, const float* dJ) {
    const int q = lane >> 2, sub = lane & 3;
    const int colbase = wc * 64;

    float rS[4] = {0, 0, 0, 0}, rA[4] = {0, 0, 0, 0}, rW[4] = {0, 0, 0, 0}, rP[4] = {0, 0, 0, 0};
#pragma unroll
    for (int n = 0; n < 8; n++) {
#pragma unroll
        for (int e = 0; e < 2; e++) {
            const int jl = colbase + n * 8 + sub * 2 + e;
            const int gj = j0 + jl;
            const unsigned long long bj = bitsJ[jl];
            const float rcj = rcJ[jl];
            const float dj = dJ[jl];
            float cS = 0.f, cA = 0.f, cW = 0.f, cP = 0.f;
#pragma unroll
            for (int g = 0; g < 4; g++) {
                const float x = acc[g >> 1][n][(g & 1) * 2 + e];
                float inter = (float)__popcll(bi4[g] & bj);
                float zr = x - di4[g];
                if (DG) {
                    const bool dg = (gi4[g] == gj);
                    inter = dg ? 0.f : inter;
                    zr = dg ? -1e30f : zr;
                }
                const float mu = inter * fminf(rci4[g], rcj);
                const float tv = mu * x;
                const float one = fminf(inter, 1.f);
                rA[g] += tv; rW[g] += mu; rP[g] += one;
                if (zr > -60.f) rS[g] += __expf(zr);
                cA += tv; cW += mu; cP += one;
                const float zc = (DG && gi4[g] == gj) ? -1e30f : x - dj;
                if (zc > -60.f) cS += __expf(zc);
            }
            if (!DG) {
#pragma unroll
                for (int o = 4; o <= 16; o <<= 1) {
                    cS += __shfl_xor_sync(0xffffffffu, cS, o);
                    cA += __shfl_xor_sync(0xffffffffu, cA, o);
                    cW += __shfl_xor_sync(0xffffffffu, cW, o);
                    cP += __shfl_xor_sync(0xffffffffu, cP, o);
                }
                if (q == 0)
                    g_col4[gj * 128 + it * 4 + wr] = make_float4(cS, cA, cW, cP);
            }
        }
    }
#pragma unroll
    for (int g = 0; g < 4; g++) {
        float S = rS[g], A = rA[g], W = rW[g], P = rP[g];
#pragma unroll
        for (int o = 1; o < 4; o <<= 1) {
            S += __shfl_xor_sync(0xffffffffu, S, o);
            A += __shfl_xor_sync(0xffffffffu, A, o);
            W += __shfl_xor_sync(0xffffffffu, W, o);
            P += __shfl_xor_sync(0xffffffffu, P, o);
        }
        if (sub == 0)
            g_row4[gi4[g] * 64 + jt * 2 + wc] = make_float4(S, A, W, P);
    }
}

// ======================= k2: persistent tile kernel (fp8, PDL) =======================
// smem: A 16KB @0, B 16KB @16384, bitsJ 1KB @32768, rcJ 512B @33792,
//       dJ 512B @34304, ticket 4B @34816.
#define SMEM_BYTES 34880

__global__ __launch_bounds__(NTHR, 2) void supcon_mma() {
    extern __shared__ char smem[];
    const uint32_t sA = smem_u32(smem);
    const uint32_t sB = sA + 16384;
    unsigned long long* bitsJ = (unsigned long long*)(smem + 32768);
    float* rcJ = (float*)(smem + 33792);
    float* dJ = (float*)(smem + 34304);
    int* s_t = (int*)(smem + 34816);

    const int tid = threadIdx.x;
    const int lane = tid & 31, wid = tid >> 5;
    const int wr = wid >> 1, wc = wid & 1;     // warp: 32 rows x 64 cols

    // PDL: launched early; wait for prep_rows' outputs (g_f8/g_bits/.../g_tick reset).
    cudaGridDependencySynchronize();

    while (true) {
        if (tid == 0) *s_t = atomicAdd(&g_tick, 1);
        __syncthreads();                        // also guards smem reuse across tiles
        const int t = *s_t;
        if (t >= NTILE) return;

        int it, jt;
        if (t < 496) {                          // off-diag first
            int u = t, r = 31; it = 0;
            while (u >= r) { u -= r; r--; it++; }
            jt = it + 1 + u;
        } else {
            it = jt = t - 496;
        }
        const int i0 = it * TM, j0 = jt * TN;

#pragma unroll
        for (int idx = tid; idx < TM * 8; idx += NTHR) {
            int row = idx >> 3, c16 = idx & 7;
            *(uint4*)(smem + swz8(row, c16)) =
                *(const uint4*)(g_f8 + (size_t)(i0 + row) * D + c16 * 16);
        }
#pragma unroll
        for (int idx = tid; idx < TN * 8; idx += NTHR) {
            int row = idx >> 3, c16 = idx & 7;
            *(uint4*)(smem + 16384 + swz8(row, c16)) =
                *(const uint4*)(g_f8 + (size_t)(j0 + row) * D + c16 * 16);
        }
#pragma unroll
        for (int x = tid; x < TN; x += NTHR) {
            bitsJ[x] = g_bits[j0 + x];
            rcJ[x] = g_rcnt[j0 + x];
            dJ[x] = g_diag[j0 + x];
        }
        __syncthreads();

        float acc[2][8][4];
#pragma unroll
        for (int m = 0; m < 2; m++)
#pragma unroll
            for (int n = 0; n < 8; n++)
#pragma unroll
                for (int c = 0; c < 4; c++) acc[m][n][c] = 0.f;

        const int lrow = lane & 15, lhalf = lane >> 4;
#pragma unroll 1
        for (int s = 0; s < 4; s++) {   // K = 4 x 32
            uint32_t a[2][4], b[4][4];
#pragma unroll
            for (int m = 0; m < 2; m++)
                ldm_x4(a[m][0], a[m][1], a[m][2], a[m][3],
                       sA + swz8(wr * 32 + m * 16 + lrow, 2 * s + lhalf));
#pragma unroll
            for (int g = 0; g < 4; g++)
                ldm_x4(b[g][0], b[g][1], b[g][2], b[g][3],
                       sB + swz8(wc * 64 + g * 16 + lrow, 2 * s + lhalf));
#pragma unroll
            for (int m = 0; m < 2; m++)
#pragma unroll
                for (int g = 0; g < 4; g++) {
                    mma16832(acc[m][2 * g + 0], a[m], b[g][0], b[g][2]);
                    mma16832(acc[m][2 * g + 1], a[m], b[g][1], b[g][3]);
                }
        }

        // per-row data + tile underflow screen
        const int q = lane >> 2;
        int gi4[4];
        unsigned long long bi4[4];
        float rci4[4], di4[4];
#pragma unroll
        for (int g = 0; g < 4; g++) {
            const int gi = i0 + wr * 32 + (g >> 1) * 16 + (g & 1) * 8 + q;
            gi4[g] = gi; bi4[g] = g_bits[gi]; rci4[g] = g_rcnt[gi]; di4[g] = g_diag[gi];
        }
        float xmax = -3.4e38f;
#pragma unroll
        for (int m = 0; m < 2; m++)
#pragma unroll
            for (int n = 0; n < 8; n++)
#pragma unroll
                for (int c = 0; c < 4; c++) xmax = fmaxf(xmax, acc[m][n][c]);
        float shmin = fminf(fminf(di4[0], di4[1]), fminf(di4[2], di4[3]));
        shmin = fminf(shmin, fminf(dJ[wc * 64 + lane], dJ[wc * 64 + 32 + lane]));
#pragma unroll
        for (int o = 1; o < 32; o <<= 1) {
            xmax = fmaxf(xmax, __shfl_xor_sync(0xffffffffu, xmax, o));
            shmin = fminf(shmin, __shfl_xor_sync(0xffffffffu, shmin, o));
        }

        if (it != jt) {
            if (xmax - shmin <= -60.f)   // every exp underflows below 9e-27 << eps
                epilogue_fast(acc, gi4, bi4, rci4, it, jt, wr, wc, lane, bitsJ, rcJ);
            else
                epilogue_slow<false>(acc, gi4, bi4, rci4, di4, i0, j0, it, jt,
                                     wr, wc, lane, bitsJ, rcJ, dJ);
        } else {
            epilogue_slow<true>(acc, gi4, bi4, rci4, di4, i0, j0, it, jt,
                                wr, wc, lane, bitsJ, rcJ, dJ);
        }
    }
}

// ======================= k3: reduce (PDL) =======================
__global__ void reduce_all(float* __restrict__ out) {
    const int lane = threadIdx.x & 31, w = threadIdx.x >> 5;
    const int row = blockIdx.x * 8 + w;
    const int b = row >> 7;

    // PDL: launched while supcon_mma drains; wait for its partials before loading.
    cudaGridDependencySynchronize();

    float S = 0.f, A = 0.f, W = 0.f, P = 0.f;
    for (int c = 2 * b + lane; c < 64; c += 32) {     // row chunks (jt >= it)
        const float4 v = g_row4[row * 64 + c];
        S += v.x; A += v.y; W += v.z; P += v.w;
    }
    for (int c = lane; c < 4 * b; c += 32) {          // col chunks (it < jt)
        const float4 v = g_col4[row * 128 + c];
        S += v.x; A += v.y; W += v.z; P += v.w;
    }
#pragma unroll
    for (int o = 16; o > 0; o >>= 1) {
        S += __shfl_xor_sync(0xffffffffu, S, o);
        A += __shfl_xor_sync(0xffffffffu, A, o);
        W += __shfl_xor_sync(0xffffffffu, W, o);
        P += __shfl_xor_sync(0xffffffffu, P, o);
    }

    __shared__ float sv[8];
    if (lane == 0) {
        const float di = g_diag[row];
        sv[w] = (A - di * W - W * logf(S + 1e-12f)) / (P + 1e-12f);
    }
    __syncthreads();

    if (w == 0) {
        float t = (lane < 8) ? sv[lane] : 0.f;
#pragma unroll
        for (int o = 4; o > 0; o >>= 1) t += __shfl_xor_sync(0xffffffffu, t, o);

        int is_last = 0;
        if (lane == 0) {
            g_part[blockIdx.x] = t;
            __threadfence();
            is_last = (atomicAdd(&g_sem, 1) == NPART - 1) ? 1 : 0;
        }
        is_last = __shfl_sync(0xffffffffu, is_last, 0);
        if (is_last) {
            __threadfence();
            float s = 0.f;
#pragma unroll
            for (int k = 0; k < NPART / 32; k++)   // fixed order -> deterministic
                s += g_part[lane + k * 32];
#pragma unroll
            for (int o = 16; o > 0; o >>= 1)
                s += __shfl_xor_sync(0xffffffffu, s, o);
            if (lane == 0)
                out[0] = -(s * (1.0f / (float)BATCH)) * 0.5f;   // -mean / 2^alpha
        }
    }
}

extern "C" void kernel_launch(void* const* d_in, const int* in_sizes, int n_in,
                              void* d_out, int out_size) {
    const float* F = (const float*)d_in[0];
    const float* L = (const float*)d_in[1];
    if (n_in >= 2 && in_sizes[0] == BATCH * 50 && in_sizes[1] == BATCH * D) {
        const float* t = F; F = L; L = t;
    }
    cudaFuncSetAttribute(supcon_mma, cudaFuncAttributeMaxDynamicSharedMemorySize, SMEM_BYTES);

    prep_rows<<<BATCH / 8, 256>>>(F, L);

    cudaLaunchAttribute pdl[1];
    pdl[0].id = cudaLaunchAttributeProgrammaticStreamSerialization;
    pdl[0].val.programmaticStreamSerializationAllowed = 1;

    cudaLaunchConfig_t cfg = {};
    cfg.gridDim = dim3(NPERS);
    cfg.blockDim = dim3(NTHR);
    cfg.dynamicSmemBytes = SMEM_BYTES;
    cfg.stream = 0;
    cfg.attrs = pdl;
    cfg.numAttrs = 1;
    cudaLaunchKernelEx(&cfg, supcon_mma);

    cudaLaunchConfig_t cfg2 = {};
    cfg2.gridDim = dim3(NPART);
    cfg2.blockDim = dim3(256);
    cfg2.stream = 0;
    cfg2.attrs = pdl;
    cfg2.numAttrs = 1;
    cudaLaunchKernelEx(&cfg2, reduce_all, (float*)d_out);
}